// round 15
// baseline (speedup 1.0000x reference)
#include <cuda_runtime.h>
#include <math.h>
#include <string.h>

#define B_ 512
#define T_ 512
#define I_ 256
#define H_ 250

// ---------------------------------------------------------------------------
// packed fp32x2 helpers
// ---------------------------------------------------------------------------
__device__ __forceinline__ unsigned long long fma2(unsigned long long a,
                                                   unsigned long long b,
                                                   unsigned long long c) {
    unsigned long long d;
    asm("fma.rn.f32x2 %0, %1, %2, %3;" : "=l"(d) : "l"(a), "l"(b), "l"(c));
    return d;
}
__device__ __forceinline__ unsigned long long add2(unsigned long long a,
                                                   unsigned long long b) {
    unsigned long long d;
    asm("add.rn.f32x2 %0, %1, %2;" : "=l"(d) : "l"(a), "l"(b));
    return d;
}
__device__ __forceinline__ float2 u2f2(unsigned long long u) {
    float2 f; memcpy(&f, &u, 8); return f;
}
__device__ __forceinline__ unsigned long long f2u2(float x, float y) {
    unsigned long long u;
    asm("mov.b64 %0, {%1, %2};" : "=l"(u) : "f"(x), "f"(y));
    return u;
}

// ---------------------------------------------------------------------------
// Kernel 1: xproj GEMM (unchanged — ~97% of scalar fma2 peak)
// ---------------------------------------------------------------------------
#define BM 128
#define BN 64
#define BK 32
#define TSTRA 36

__global__ __launch_bounds__(256, 2) void xproj_kernel(
    const float* __restrict__ x, const float* __restrict__ Wx,
    const float* __restrict__ bh, float* __restrict__ out)
{
    __shared__ float As[BM][TSTRA];
    __shared__ float Bs[BN][TSTRA];

    const int m0  = blockIdx.x * BM;
    const int n0  = blockIdx.y * BN;
    const int tid = threadIdx.x;
    const int tn  = tid & 15;
    const int tm  = tid >> 4;

    unsigned long long acc[8][4];
#pragma unroll
    for (int i = 0; i < 8; i++)
#pragma unroll
        for (int j = 0; j < 4; j++) acc[i][j] = 0ull;

    const int ar = tid >> 3;
    const int ac = (tid & 7) * 4;

    for (int k0 = 0; k0 < I_; k0 += BK) {
#pragma unroll
        for (int p = 0; p < 4; p++) {
            int row = p * 32 + ar;
            float4 v = *(const float4*)(x + (size_t)(m0 + row) * I_ + k0 + ac);
            *(float4*)&As[row][ac] = v;
        }
#pragma unroll
        for (int p = 0; p < 2; p++) {
            int row = p * 32 + ar;
            int n = n0 + row;
            float4 v = make_float4(0.f, 0.f, 0.f, 0.f);
            if (n < H_) v = *(const float4*)(Wx + (size_t)n * I_ + k0 + ac);
            *(float4*)&Bs[row][ac] = v;
        }
        __syncthreads();

#pragma unroll
        for (int j = 0; j < BK / 4; j++) {
            ulonglong2 b[4];
#pragma unroll
            for (int nn = 0; nn < 4; nn++)
                b[nn] = *(const ulonglong2*)&Bs[tn * 4 + nn][4 * j];
#pragma unroll
            for (int mm = 0; mm < 8; mm++) {
                ulonglong2 a = *(const ulonglong2*)&As[tm * 8 + mm][4 * j];
#pragma unroll
                for (int nn = 0; nn < 4; nn++) {
                    acc[mm][nn] = fma2(a.x, b[nn].x, acc[mm][nn]);
                    acc[mm][nn] = fma2(a.y, b[nn].y, acc[mm][nn]);
                }
            }
        }
        __syncthreads();
    }

#pragma unroll
    for (int nn = 0; nn < 4; nn++) {
        int n = n0 + tn * 4 + nn;
        if (n >= H_) continue;
        float bias = bh[n];
#pragma unroll
        for (int mm = 0; mm < 8; mm++) {
            int m = m0 + tm * 8 + mm;
            float2 f = u2f2(acc[mm][nn]);
            out[(size_t)m * H_ + n] = f.x + f.y + bias;
        }
    }
}

// ---------------------------------------------------------------------------
// Kernel 2: recurrence rec6 — k-pair packed f32x2, zero per-step movs.
//   128 CTAs x 256 threads, CTA = 4 batches.
//   thread (rg = t>>3, ks = t&7): 8 rows (8rg..8rg+7), k-pair slice
//   {pair p == ks mod 8}. Main k<224: weights in smem, row stride 226
//   (== 2 mod 4 -> LDS.64 bank-uniform 2-phase); per j: 4 hp LDS.64
//   (dedup, 1 wf) + 8 w LDS.64 (2 wf) + 32 fma2, all literal offsets.
//   Tail k in [224,256): 16 pre-packed k-pair regs. hp layout [b][256].
//   Reduce-scatter over ks (3 shfl.64 stages, 4 batch channels); lane
//   finalizes row 8rg+ks: 4 tanh + 4 STG + 4 STS.32. Two barriers/step.
// ---------------------------------------------------------------------------
#define WST6  226          // weight row stride (floats), == 2 mod 4
#define MK6   224          // main k extent in smem
#define HPS6  256          // hp row stride per batch
#define HPOF6 56500        // 250*226 floats; *4 bytes % 16 == 0 (16B aligned)

__global__ __launch_bounds__(256, 1) void rnn_rec6(
    const float* __restrict__ h0, const float* __restrict__ Wh,
    float* __restrict__ out)
{
    extern __shared__ float sm[];
    float* Wsm = sm;                    // 250 rows * 226 floats
    float* hp  = sm + HPOF6;            // 4 * 256 floats, 16B-aligned

    const int t  = threadIdx.x;
    const int rg = t >> 3;              // 0..31
    const int ks = t & 7;
    const int b0 = blockIdx.x * 4;

    // weights k<224 into smem
    for (int idx = t; idx < H_ * MK6; idx += 256) {
        int r = idx / MK6, k = idx - r * MK6;
        Wsm[r * WST6 + k] = Wh[(size_t)r * H_ + k];
    }
    // tail weights k in [224,256): pair q = ks + 8i, k = 224 + 2q
    // pre-packed as k-pairs: NO per-step movs
    unsigned long long tw2[8][2];
#pragma unroll
    for (int rr = 0; rr < 8; rr++) {
        int r = rg * 8 + rr;
#pragma unroll
        for (int i = 0; i < 2; i++) {
            int k = MK6 + 2 * (ks + 8 * i);
            float wa = (r < H_ && k     < H_) ? Wh[(size_t)r * H_ + k]     : 0.f;
            float wb = (r < H_ && k + 1 < H_) ? Wh[(size_t)r * H_ + k + 1] : 0.f;
            tw2[rr][i] = f2u2(wa, wb);
        }
    }
    // hp init: hp[b*256 + k]; k >= 250 zero (never rewritten; tail w zero)
    for (int idx = t; idx < 4 * HPS6; idx += 256) {
        int b = idx >> 8, k = idx & 255;
        hp[idx] = (k < H_) ? h0[(size_t)(b0 + b) * H_ + k] : 0.f;
    }
    __syncthreads();

    // per-row weight base pointers (row clamped to 249 for dummy slots;
    // +2ks folded in -> per-j literal offset = 16 floats)
    const float* wr[8];
#pragma unroll
    for (int rr = 0; rr < 8; rr++) {
        int r = rg * 8 + rr; if (r > H_ - 1) r = H_ - 1;
        wr[rr] = Wsm + r * WST6 + 2 * ks;
    }
    const float* hpp = hp + 2 * ks;
    const int  rfin = rg * 8 + ks;
    const bool fact = (rfin < H_);

    for (int ts = 0; ts < T_; ts++) {
        // prefetch xproj values (warp covers 32 consecutive rows: coalesced)
        float xp[4];
        if (fact) {
#pragma unroll
            for (int b = 0; b < 4; b++)
                xp[b] = out[((size_t)(b0 + b) * T_ + ts) * H_ + rfin];
        }

        unsigned long long acc[8][4];
#pragma unroll
        for (int rr = 0; rr < 8; rr++)
#pragma unroll
            for (int b = 0; b < 4; b++) acc[rr][b] = 0ull;

        // main: k-pair = ks + 8j, j < 14 (k = 2ks + 16j)
#pragma unroll
        for (int j = 0; j < MK6 / 16; j++) {
            unsigned long long h2[4];
#pragma unroll
            for (int b = 0; b < 4; b++)
                h2[b] = *(const unsigned long long*)(hpp + b * HPS6 + 16 * j);
#pragma unroll
            for (int rr = 0; rr < 8; rr++) {
                unsigned long long w2 =
                    *(const unsigned long long*)(wr[rr] + 16 * j);
                acc[rr][0] = fma2(w2, h2[0], acc[rr][0]);
                acc[rr][1] = fma2(w2, h2[1], acc[rr][1]);
                acc[rr][2] = fma2(w2, h2[2], acc[rr][2]);
                acc[rr][3] = fma2(w2, h2[3], acc[rr][3]);
            }
        }
        // tail: k = 224 + 2(ks + 8i), i < 2 (weights pre-packed in regs)
#pragma unroll
        for (int i = 0; i < 2; i++) {
            unsigned long long h2[4];
#pragma unroll
            for (int b = 0; b < 4; b++)
                h2[b] = *(const unsigned long long*)(hpp + b * HPS6 + MK6 + 16 * i);
#pragma unroll
            for (int rr = 0; rr < 8; rr++) {
                acc[rr][0] = fma2(tw2[rr][i], h2[0], acc[rr][0]);
                acc[rr][1] = fma2(tw2[rr][i], h2[1], acc[rr][1]);
                acc[rr][2] = fma2(tw2[rr][i], h2[2], acc[rr][2]);
                acc[rr][3] = fma2(tw2[rr][i], h2[3], acc[rr][3]);
            }
        }

        // reduce-scatter over ks bits {4,2,1}, 4 batch channels:
        // lane ends with row (8rg+ks) sums (k-parity still packed)
        unsigned long long fin[4];
        {
            unsigned long long w1[4][4], w2s[2][4];
#pragma unroll
            for (int i = 0; i < 4; i++)
#pragma unroll
                for (int b = 0; b < 4; b++) {
                    unsigned long long snd = (ks & 4) ? acc[i][b] : acc[i + 4][b];
                    unsigned long long rcv = __shfl_xor_sync(0xffffffffu, snd, 4);
                    unsigned long long kp  = (ks & 4) ? acc[i + 4][b] : acc[i][b];
                    w1[i][b] = add2(kp, rcv);
                }
#pragma unroll
            for (int i = 0; i < 2; i++)
#pragma unroll
                for (int b = 0; b < 4; b++) {
                    unsigned long long snd = (ks & 2) ? w1[i][b] : w1[i + 2][b];
                    unsigned long long rcv = __shfl_xor_sync(0xffffffffu, snd, 2);
                    unsigned long long kp  = (ks & 2) ? w1[i + 2][b] : w1[i][b];
                    w2s[i][b] = add2(kp, rcv);
                }
#pragma unroll
            for (int b = 0; b < 4; b++) {
                unsigned long long snd = (ks & 1) ? w2s[0][b] : w2s[1][b];
                unsigned long long rcv = __shfl_xor_sync(0xffffffffu, snd, 1);
                unsigned long long kp  = (ks & 1) ? w2s[1][b] : w2s[0][b];
                fin[b] = add2(kp, rcv);
            }
        }

        __syncthreads();   // all hp reads of this step complete

        if (fact) {
            float v[4];
#pragma unroll
            for (int b = 0; b < 4; b++) {
                float2 f = u2f2(fin[b]);
                v[b] = tanhf(xp[b] + f.x + f.y);
            }
#pragma unroll
            for (int b = 0; b < 4; b++)
                out[((size_t)(b0 + b) * T_ + ts) * H_ + rfin] = v[b];
#pragma unroll
            for (int b = 0; b < 4; b++)
                hp[b * HPS6 + rfin] = v[b];
        }
        __syncthreads();   // hp writes visible before next step's reads
    }
}

// ---------------------------------------------------------------------------
extern "C" void kernel_launch(void* const* d_in, const int* in_sizes, int n_in,
                              void* d_out, int out_size)
{
    const float* x  = (const float*)d_in[0];
    const float* h0 = (const float*)d_in[1];
    const float* Wx = (const float*)d_in[2];
    const float* Wh = (const float*)d_in[3];
    const float* bh = (const float*)d_in[4];
    float* out = (float*)d_out;

    static int attr_done = 0;
    size_t smem2 = (size_t)(HPOF6 + 4 * HPS6) * sizeof(float);
    if (!attr_done) {
        cudaFuncSetAttribute(rnn_rec6,
                             cudaFuncAttributeMaxDynamicSharedMemorySize,
                             (int)smem2);
        attr_done = 1;
    }

    // 1) xproj + bias into d_out (scratch reuse)
    dim3 g1((B_ * T_) / BM, (H_ + BN - 1) / BN);
    xproj_kernel<<<g1, 256>>>(x, Wx, bh, out);

    // 2) recurrence: 128 CTAs x 256 threads, in-place on d_out
    rnn_rec6<<<B_ / 4, 256, smem2>>>(h0, Wh, out);
}

// round 17
// speedup vs baseline: 1.4903x; 1.4903x over previous
#include <cuda_runtime.h>
#include <cuda_bf16.h>
#include <mma.h>
#include <math.h>
#include <string.h>

using namespace nvcuda;

#define B_ 512
#define T_ 512
#define I_ 256
#define H_ 250

// ---------------------------------------------------------------------------
// packed fp32x2 helpers
// ---------------------------------------------------------------------------
__device__ __forceinline__ unsigned long long fma2(unsigned long long a,
                                                   unsigned long long b,
                                                   unsigned long long c) {
    unsigned long long d;
    asm("fma.rn.f32x2 %0, %1, %2, %3;" : "=l"(d) : "l"(a), "l"(b), "l"(c));
    return d;
}
__device__ __forceinline__ unsigned long long add2(unsigned long long a,
                                                   unsigned long long b) {
    unsigned long long d;
    asm("add.rn.f32x2 %0, %1, %2;" : "=l"(d) : "l"(a), "l"(b));
    return d;
}
__device__ __forceinline__ float2 u2f2(unsigned long long u) {
    float2 f; memcpy(&f, &u, 8); return f;
}
__device__ __forceinline__ unsigned long long f2u2(float x, float y) {
    unsigned long long u;
    asm("mov.b64 %0, {%1, %2};" : "=l"(u) : "f"(x), "f"(y));
    return u;
}

// ---------------------------------------------------------------------------
// Kernel 1: xproj on tensor cores.  out[m,n] = sum_k x[m,k]*Wx[n,k] + bh[n]
//   bf16 3-term split (xh*wh + xh*wl + xl*wh), fp32 accumulate.
//   CTA 128x64, 8 warps (4x2), warp tile 32x32 = 2x2 wmma 16x16x16 frags.
//   K staged 16 at a time; epilogue C staged in smem (aliases A/B tiles),
//   coalesced column-per-lane stores with bias, predicated n<250.
//   NOTE: all wmma ldm values are multiples of 16 bytes (ASTR=24 bf16=48B,
//   CSTR=36 f32=144B) per the wmma alignment requirement.
// ---------------------------------------------------------------------------
#define XBM 128
#define XBN 64
#define XBK 16
#define ASTR 24          // bf16 tile row stride: 48B, 16B-multiple
#define CSTR 36          // fp32 C staging stride: 144B, 16B-multiple

__device__ __forceinline__ void split_bf16(float v, __nv_bfloat16& h,
                                           __nv_bfloat16& l) {
    h = __float2bfloat16(v);
    l = __float2bfloat16(v - __bfloat162float(h));
}

__global__ __launch_bounds__(256) void xproj_tc(
    const float* __restrict__ x, const float* __restrict__ Wx,
    const float* __restrict__ bh, float* __restrict__ out)
{
    extern __shared__ char smraw[];
    __nv_bfloat16* Ah = (__nv_bfloat16*)smraw;       // 128*24
    __nv_bfloat16* Al = Ah + XBM * ASTR;             // 128*24
    __nv_bfloat16* Bh = Al + XBM * ASTR;             // 64*24
    __nv_bfloat16* Bl = Bh + XBN * ASTR;             // 64*24
    float* Cs = (float*)smraw;                       // epilogue alias: 8*32*36

    const int m0  = blockIdx.x * XBM;
    const int n0  = blockIdx.y * XBN;
    const int tid = threadIdx.x;
    const int wid = tid >> 5;
    const int lane = tid & 31;
    const int wm = wid >> 1;        // 0..3
    const int wn = wid & 1;         // 0..1

    wmma::fragment<wmma::accumulator, 16, 16, 16, float> acc[2][2];
#pragma unroll
    for (int i = 0; i < 2; i++)
#pragma unroll
        for (int j = 0; j < 2; j++) wmma::fill_fragment(acc[i][j], 0.f);

    const int arow = tid >> 1;          // 0..127
    const int akq  = (tid & 1) * 8;     // 0 or 8

    for (int k0 = 0; k0 < I_; k0 += XBK) {
        __syncthreads();   // previous iter's frag loads done before refill

        // A tile: x[m0+row][k0..k0+16), split into hi/lo bf16
        {
            const float* src = x + (size_t)(m0 + arow) * I_ + k0 + akq;
            float4 v0 = *(const float4*)(src);
            float4 v1 = *(const float4*)(src + 4);
            __nv_bfloat16* ph = Ah + arow * ASTR + akq;
            __nv_bfloat16* pl = Al + arow * ASTR + akq;
            float vv[8] = {v0.x, v0.y, v0.z, v0.w, v1.x, v1.y, v1.z, v1.w};
#pragma unroll
            for (int q = 0; q < 8; q++) split_bf16(vv[q], ph[q], pl[q]);
        }
        // B tile: Wx[n0+row][k0..k0+16), predicated n<250 (zeros otherwise)
        if (tid < 128) {
            int row = tid >> 1;
            int n = n0 + row;
            int kq = (tid & 1) * 8;
            float vv[8] = {0.f, 0.f, 0.f, 0.f, 0.f, 0.f, 0.f, 0.f};
            if (n < H_) {
                const float* src = Wx + (size_t)n * I_ + k0 + kq;
                float4 v0 = *(const float4*)(src);
                float4 v1 = *(const float4*)(src + 4);
                vv[0] = v0.x; vv[1] = v0.y; vv[2] = v0.z; vv[3] = v0.w;
                vv[4] = v1.x; vv[5] = v1.y; vv[6] = v1.z; vv[7] = v1.w;
            }
            __nv_bfloat16* ph = Bh + row * ASTR + kq;
            __nv_bfloat16* pl = Bl + row * ASTR + kq;
#pragma unroll
            for (int q = 0; q < 8; q++) split_bf16(vv[q], ph[q], pl[q]);
        }
        __syncthreads();

        wmma::fragment<wmma::matrix_a, 16, 16, 16, __nv_bfloat16,
                       wmma::row_major> a_h, a_l;
        wmma::fragment<wmma::matrix_b, 16, 16, 16, __nv_bfloat16,
                       wmma::col_major> b_h, b_l;
#pragma unroll
        for (int i = 0; i < 2; i++) {
            wmma::load_matrix_sync(a_h, Ah + (wm * 32 + i * 16) * ASTR, ASTR);
            wmma::load_matrix_sync(a_l, Al + (wm * 32 + i * 16) * ASTR, ASTR);
#pragma unroll
            for (int j = 0; j < 2; j++) {
                wmma::load_matrix_sync(b_h, Bh + (wn * 32 + j * 16) * ASTR, ASTR);
                wmma::load_matrix_sync(b_l, Bl + (wn * 32 + j * 16) * ASTR, ASTR);
                wmma::mma_sync(acc[i][j], a_h, b_h, acc[i][j]);
                wmma::mma_sync(acc[i][j], a_h, b_l, acc[i][j]);
                wmma::mma_sync(acc[i][j], a_l, b_h, acc[i][j]);
            }
        }
    }

    __syncthreads();   // all warps done with A/B smem before Cs alias

    // stage C in smem (per-warp region), then coalesced store with bias
    float* cw = Cs + wid * (32 * CSTR);
#pragma unroll
    for (int i = 0; i < 2; i++)
#pragma unroll
        for (int j = 0; j < 2; j++)
            wmma::store_matrix_sync(cw + (i * 16) * CSTR + j * 16,
                                    acc[i][j], CSTR, wmma::mem_row_major);
    __syncwarp();

    int n = n0 + wn * 32 + lane;
    if (n < H_) {
        float bias = bh[n];
        int mbase = m0 + wm * 32;
#pragma unroll 4
        for (int r = 0; r < 32; r++)
            out[(size_t)(mbase + r) * H_ + n] = cw[r * CSTR + lane] + bias;
    }
}

// ---------------------------------------------------------------------------
// Kernel 2: recurrence rec6 (unchanged — current best)
// ---------------------------------------------------------------------------
#define WST6  226
#define MK6   224
#define HPS6  256
#define HPOF6 56500

__global__ __launch_bounds__(256, 1) void rnn_rec6(
    const float* __restrict__ h0, const float* __restrict__ Wh,
    float* __restrict__ out)
{
    extern __shared__ float sm[];
    float* Wsm = sm;
    float* hp  = sm + HPOF6;

    const int t  = threadIdx.x;
    const int rg = t >> 3;
    const int ks = t & 7;
    const int b0 = blockIdx.x * 4;

    for (int idx = t; idx < H_ * MK6; idx += 256) {
        int r = idx / MK6, k = idx - r * MK6;
        Wsm[r * WST6 + k] = Wh[(size_t)r * H_ + k];
    }
    unsigned long long tw2[8][2];
#pragma unroll
    for (int rr = 0; rr < 8; rr++) {
        int r = rg * 8 + rr;
#pragma unroll
        for (int i = 0; i < 2; i++) {
            int k = MK6 + 2 * (ks + 8 * i);
            float wa = (r < H_ && k     < H_) ? Wh[(size_t)r * H_ + k]     : 0.f;
            float wb = (r < H_ && k + 1 < H_) ? Wh[(size_t)r * H_ + k + 1] : 0.f;
            tw2[rr][i] = f2u2(wa, wb);
        }
    }
    for (int idx = t; idx < 4 * HPS6; idx += 256) {
        int b = idx >> 8, k = idx & 255;
        hp[idx] = (k < H_) ? h0[(size_t)(b0 + b) * H_ + k] : 0.f;
    }
    __syncthreads();

    const float* wr[8];
#pragma unroll
    for (int rr = 0; rr < 8; rr++) {
        int r = rg * 8 + rr; if (r > H_ - 1) r = H_ - 1;
        wr[rr] = Wsm + r * WST6 + 2 * ks;
    }
    const float* hpp = hp + 2 * ks;
    const int  rfin = rg * 8 + ks;
    const bool fact = (rfin < H_);

    for (int ts = 0; ts < T_; ts++) {
        float xp[4];
        if (fact) {
#pragma unroll
            for (int b = 0; b < 4; b++)
                xp[b] = out[((size_t)(b0 + b) * T_ + ts) * H_ + rfin];
        }

        unsigned long long acc[8][4];
#pragma unroll
        for (int rr = 0; rr < 8; rr++)
#pragma unroll
            for (int b = 0; b < 4; b++) acc[rr][b] = 0ull;

#pragma unroll
        for (int j = 0; j < MK6 / 16; j++) {
            unsigned long long h2[4];
#pragma unroll
            for (int b = 0; b < 4; b++)
                h2[b] = *(const unsigned long long*)(hpp + b * HPS6 + 16 * j);
#pragma unroll
            for (int rr = 0; rr < 8; rr++) {
                unsigned long long w2 =
                    *(const unsigned long long*)(wr[rr] + 16 * j);
                acc[rr][0] = fma2(w2, h2[0], acc[rr][0]);
                acc[rr][1] = fma2(w2, h2[1], acc[rr][1]);
                acc[rr][2] = fma2(w2, h2[2], acc[rr][2]);
                acc[rr][3] = fma2(w2, h2[3], acc[rr][3]);
            }
        }
#pragma unroll
        for (int i = 0; i < 2; i++) {
            unsigned long long h2[4];
#pragma unroll
            for (int b = 0; b < 4; b++)
                h2[b] = *(const unsigned long long*)(hpp + b * HPS6 + MK6 + 16 * i);
#pragma unroll
            for (int rr = 0; rr < 8; rr++) {
                acc[rr][0] = fma2(tw2[rr][i], h2[0], acc[rr][0]);
                acc[rr][1] = fma2(tw2[rr][i], h2[1], acc[rr][1]);
                acc[rr][2] = fma2(tw2[rr][i], h2[2], acc[rr][2]);
                acc[rr][3] = fma2(tw2[rr][i], h2[3], acc[rr][3]);
            }
        }

        unsigned long long fin[4];
        {
            unsigned long long w1[4][4], w2s[2][4];
#pragma unroll
            for (int i = 0; i < 4; i++)
#pragma unroll
                for (int b = 0; b < 4; b++) {
                    unsigned long long snd = (ks & 4) ? acc[i][b] : acc[i + 4][b];
                    unsigned long long rcv = __shfl_xor_sync(0xffffffffu, snd, 4);
                    unsigned long long kp  = (ks & 4) ? acc[i + 4][b] : acc[i][b];
                    w1[i][b] = add2(kp, rcv);
                }
#pragma unroll
            for (int i = 0; i < 2; i++)
#pragma unroll
                for (int b = 0; b < 4; b++) {
                    unsigned long long snd = (ks & 2) ? w1[i][b] : w1[i + 2][b];
                    unsigned long long rcv = __shfl_xor_sync(0xffffffffu, snd, 2);
                    unsigned long long kp  = (ks & 2) ? w1[i + 2][b] : w1[i][b];
                    w2s[i][b] = add2(kp, rcv);
                }
#pragma unroll
            for (int b = 0; b < 4; b++) {
                unsigned long long snd = (ks & 1) ? w2s[0][b] : w2s[1][b];
                unsigned long long rcv = __shfl_xor_sync(0xffffffffu, snd, 1);
                unsigned long long kp  = (ks & 1) ? w2s[1][b] : w2s[0][b];
                fin[b] = add2(kp, rcv);
            }
        }

        __syncthreads();

        if (fact) {
            float v[4];
#pragma unroll
            for (int b = 0; b < 4; b++) {
                float2 f = u2f2(fin[b]);
                v[b] = tanhf(xp[b] + f.x + f.y);
            }
#pragma unroll
            for (int b = 0; b < 4; b++)
                out[((size_t)(b0 + b) * T_ + ts) * H_ + rfin] = v[b];
#pragma unroll
            for (int b = 0; b < 4; b++)
                hp[b * HPS6 + rfin] = v[b];
        }
        __syncthreads();
    }
}

// ---------------------------------------------------------------------------
extern "C" void kernel_launch(void* const* d_in, const int* in_sizes, int n_in,
                              void* d_out, int out_size)
{
    const float* x  = (const float*)d_in[0];
    const float* h0 = (const float*)d_in[1];
    const float* Wx = (const float*)d_in[2];
    const float* Wh = (const float*)d_in[3];
    const float* bh = (const float*)d_in[4];
    float* out = (float*)d_out;

    static int attr_done = 0;
    size_t smem2 = (size_t)(HPOF6 + 4 * HPS6) * sizeof(float);
    if (!attr_done) {
        cudaFuncSetAttribute(rnn_rec6,
                             cudaFuncAttributeMaxDynamicSharedMemorySize,
                             (int)smem2);
        attr_done = 1;
    }

    // 1) xproj on tensor cores (bf16 3-term split), into d_out
    size_t smem1a = (size_t)(2 * XBM * ASTR + 2 * XBN * ASTR) * sizeof(__nv_bfloat16);
    size_t smem1b = (size_t)(8 * 32 * CSTR) * sizeof(float);
    size_t smem1  = smem1a > smem1b ? smem1a : smem1b;
    dim3 g1((B_ * T_) / XBM, (H_ + XBN - 1) / XBN);
    xproj_tc<<<g1, 256, smem1>>>(x, Wx, bh, out);

    // 2) recurrence: 128 CTAs x 256 threads, in-place on d_out
    rnn_rec6<<<B_ / 4, 256, smem2>>>(h0, Wh, out);
}